// round 1
// baseline (speedup 1.0000x reference)
#include <cuda_runtime.h>
#include <cuda_bf16.h>
#include <cstdio>

// Problem constants
#define BB   2
#define SS   2048
#define EE   2048
#define HQ   32
#define HKV  8
#define HD   64
#define KV   512
#define MM   (BB*SS)         // 4096
#define SCALE 0.125f         // 1/sqrt(64)

// Scratch (device globals; no allocation allowed)
__device__ float g_Q[MM*EE];    // (B*S, E)  projected Q
__device__ float g_K[MM*KV];    // (B*S, KV) projected K
__device__ float g_V[MM*KV];    // (B*S, KV) projected V
__device__ float g_CTX[MM*EE];  // attention context before Wo

// ---------------------------------------------------------------------------
// Generic SGEMM + bias: C[M,N] = A[M,K] @ W[K,N] + b[N]
// BM=128, BN=128, BK=16, 256 threads, 8x8 microtile.
// ---------------------------------------------------------------------------
__global__ __launch_bounds__(256) void sgemm_bias_kernel(
    const float* __restrict__ A, const float* __restrict__ W,
    const float* __restrict__ bias, float* __restrict__ C,
    int M, int N, int K)
{
    __shared__ float As[16][128];
    __shared__ float Ws[16][128];

    const int tid = threadIdx.x;
    const int block_row = blockIdx.y * 128;
    const int block_col = blockIdx.x * 128;

    const int trow = (tid / 16) * 8;
    const int tcol = (tid % 16) * 8;

    float acc[8][8];
#pragma unroll
    for (int i = 0; i < 8; i++)
#pragma unroll
        for (int j = 0; j < 8; j++) acc[i][j] = 0.f;

    for (int k0 = 0; k0 < K; k0 += 16) {
        // Load A tile (128x16) transposed into As[k][m]
#pragma unroll
        for (int it = 0; it < 2; it++) {
            int idx = tid + it * 256;
            int r = idx >> 2;           // 0..127
            int c = (idx & 3) * 4;      // 0..12
            float4 v = *(const float4*)&A[(size_t)(block_row + r) * K + k0 + c];
            As[c + 0][r] = v.x;
            As[c + 1][r] = v.y;
            As[c + 2][r] = v.z;
            As[c + 3][r] = v.w;
        }
        // Load W tile (16x128) direct into Ws[k][n]
#pragma unroll
        for (int it = 0; it < 2; it++) {
            int idx = tid + it * 256;
            int r = idx >> 5;           // 0..15
            int c = (idx & 31) * 4;     // 0..124
            *(float4*)&Ws[r][c] = *(const float4*)&W[(size_t)(k0 + r) * N + block_col + c];
        }
        __syncthreads();

#pragma unroll
        for (int kk = 0; kk < 16; kk++) {
            float a[8], w[8];
            *(float4*)&a[0] = *(const float4*)&As[kk][trow];
            *(float4*)&a[4] = *(const float4*)&As[kk][trow + 4];
            *(float4*)&w[0] = *(const float4*)&Ws[kk][tcol];
            *(float4*)&w[4] = *(const float4*)&Ws[kk][tcol + 4];
#pragma unroll
            for (int i = 0; i < 8; i++)
#pragma unroll
                for (int j = 0; j < 8; j++) acc[i][j] += a[i] * w[j];
        }
        __syncthreads();
    }

#pragma unroll
    for (int i = 0; i < 8; i++) {
#pragma unroll
        for (int j = 0; j < 8; j += 4) {
            float4 v;
            v.x = acc[i][j + 0] + bias[block_col + tcol + j + 0];
            v.y = acc[i][j + 1] + bias[block_col + tcol + j + 1];
            v.z = acc[i][j + 2] + bias[block_col + tcol + j + 2];
            v.w = acc[i][j + 3] + bias[block_col + tcol + j + 3];
            *(float4*)&C[(size_t)(block_row + trow + i) * N + block_col + tcol + j] = v;
        }
    }
}

// ---------------------------------------------------------------------------
// Scores: attn[b,hq,sq,sk] = scale * sum_d Q[b,sq,hq,d] * K[b,sk,hq/4,d]
// One block computes a 64x64 (sq,sk) tile for one (b,hq). Inner K-dim = 64.
// ---------------------------------------------------------------------------
__global__ __launch_bounds__(256) void scores_kernel(
    const float* __restrict__ Q, const float* __restrict__ K,
    float* __restrict__ attn)
{
    const int bh = blockIdx.z;            // b*32 + hq
    const int b = bh >> 5;
    const int hq = bh & 31;
    const int hkv = hq >> 2;
    const int sq0 = blockIdx.y * 64;
    const int sk0 = blockIdx.x * 64;

    __shared__ float Qs[64][65];          // [d][sq]
    __shared__ float Ks[64][65];          // [d][sk]

    const int tid = threadIdx.x;

    // Load Q tile: 64 rows (sq) x 64 cols (d), store transposed
#pragma unroll
    for (int it = 0; it < 4; it++) {
        int idx = tid + it * 256;
        int r = idx >> 4;               // sq offset 0..63
        int c = (idx & 15) * 4;         // d offset
        float4 v = *(const float4*)&Q[(size_t)(b * SS + sq0 + r) * EE + hq * HD + c];
        Qs[c + 0][r] = v.x;
        Qs[c + 1][r] = v.y;
        Qs[c + 2][r] = v.z;
        Qs[c + 3][r] = v.w;
    }
    // Load K tile likewise
#pragma unroll
    for (int it = 0; it < 4; it++) {
        int idx = tid + it * 256;
        int r = idx >> 4;               // sk offset
        int c = (idx & 15) * 4;
        float4 v = *(const float4*)&K[(size_t)(b * SS + sk0 + r) * KV + hkv * HD + c];
        Ks[c + 0][r] = v.x;
        Ks[c + 1][r] = v.y;
        Ks[c + 2][r] = v.z;
        Ks[c + 3][r] = v.w;
    }
    __syncthreads();

    const int trow = (tid / 16) * 4;
    const int tcol = (tid % 16) * 4;
    float acc[4][4];
#pragma unroll
    for (int i = 0; i < 4; i++)
#pragma unroll
        for (int j = 0; j < 4; j++) acc[i][j] = 0.f;

#pragma unroll
    for (int d = 0; d < 64; d++) {
        float a[4], k[4];
#pragma unroll
        for (int i = 0; i < 4; i++) a[i] = Qs[d][trow + i];
#pragma unroll
        for (int j = 0; j < 4; j++) k[j] = Ks[d][tcol + j];
#pragma unroll
        for (int i = 0; i < 4; i++)
#pragma unroll
            for (int j = 0; j < 4; j++) acc[i][j] += a[i] * k[j];
    }

    float* base = attn + ((size_t)bh * SS + sq0) * SS + sk0;
#pragma unroll
    for (int i = 0; i < 4; i++) {
        float4 v;
        v.x = acc[i][0] * SCALE;
        v.y = acc[i][1] * SCALE;
        v.z = acc[i][2] * SCALE;
        v.w = acc[i][3] * SCALE;
        *(float4*)&base[(size_t)(trow + i) * SS + tcol] = v;
    }
}

// ---------------------------------------------------------------------------
// In-place row softmax over last dim (2048). One block (256 thr) per row.
// ---------------------------------------------------------------------------
__global__ __launch_bounds__(256) void softmax_kernel(float* __restrict__ attn)
{
    float* p = attn + (size_t)blockIdx.x * SS;
    const int t = threadIdx.x;

    float4 a = ((float4*)p)[t];
    float4 b = ((float4*)p)[t + 256];

    float m = fmaxf(fmaxf(fmaxf(a.x, a.y), fmaxf(a.z, a.w)),
                    fmaxf(fmaxf(b.x, b.y), fmaxf(b.z, b.w)));
#pragma unroll
    for (int o = 16; o; o >>= 1) m = fmaxf(m, __shfl_xor_sync(0xffffffffu, m, o));

    __shared__ float sm[8], ssum[8];
    if ((t & 31) == 0) sm[t >> 5] = m;
    __syncthreads();
    m = sm[0];
#pragma unroll
    for (int i = 1; i < 8; i++) m = fmaxf(m, sm[i]);

    a.x = __expf(a.x - m); a.y = __expf(a.y - m);
    a.z = __expf(a.z - m); a.w = __expf(a.w - m);
    b.x = __expf(b.x - m); b.y = __expf(b.y - m);
    b.z = __expf(b.z - m); b.w = __expf(b.w - m);

    float s = a.x + a.y + a.z + a.w + b.x + b.y + b.z + b.w;
#pragma unroll
    for (int o = 16; o; o >>= 1) s += __shfl_xor_sync(0xffffffffu, s, o);
    if ((t & 31) == 0) ssum[t >> 5] = s;
    __syncthreads();
    s = 0.f;
#pragma unroll
    for (int i = 0; i < 8; i++) s += ssum[i];

    const float inv = 1.0f / s;
    a.x *= inv; a.y *= inv; a.z *= inv; a.w *= inv;
    b.x *= inv; b.y *= inv; b.z *= inv; b.w *= inv;
    ((float4*)p)[t] = a;
    ((float4*)p)[t + 256] = b;
}

// ---------------------------------------------------------------------------
// AV: ctx[b,sq,hq*64+d] = sum_sk attn[b,hq,sq,sk] * V[b,sk,hq/4,d]
// One block: 64 sq rows x 64 d cols for one (b,hq); loop over sk in BK=32.
// ---------------------------------------------------------------------------
__global__ __launch_bounds__(256) void av_kernel(
    const float* __restrict__ attn, const float* __restrict__ V,
    float* __restrict__ ctx)
{
    const int bh = blockIdx.z;
    const int b = bh >> 5;
    const int hq = bh & 31;
    const int hkv = hq >> 2;
    const int sq0 = blockIdx.y * 64;

    __shared__ float As[32][65];   // [sk][sq] (transposed attn tile)
    __shared__ float Vs[32][68];   // [sk][d]

    const int tid = threadIdx.x;
    const int trow = (tid / 16) * 4;
    const int tcol = (tid % 16) * 4;

    const float* abase = attn + ((size_t)bh * SS + sq0) * SS;

    float acc[4][4];
#pragma unroll
    for (int i = 0; i < 4; i++)
#pragma unroll
        for (int j = 0; j < 4; j++) acc[i][j] = 0.f;

    for (int k0 = 0; k0 < SS; k0 += 32) {
        // attn tile: 64 (sq) x 32 (sk), store transposed
#pragma unroll
        for (int it = 0; it < 2; it++) {
            int idx = tid + it * 256;
            int r = idx >> 3;            // sq 0..63
            int c = (idx & 7) * 4;       // sk 0..28
            float4 v = *(const float4*)&abase[(size_t)r * SS + k0 + c];
            As[c + 0][r] = v.x;
            As[c + 1][r] = v.y;
            As[c + 2][r] = v.z;
            As[c + 3][r] = v.w;
        }
        // V tile: 32 (sk) x 64 (d)
#pragma unroll
        for (int it = 0; it < 2; it++) {
            int idx = tid + it * 256;
            int r = idx >> 4;            // sk 0..31
            int c = (idx & 15) * 4;      // d
            *(float4*)&Vs[r][c] =
                *(const float4*)&V[(size_t)(b * SS + k0 + r) * KV + hkv * HD + c];
        }
        __syncthreads();

#pragma unroll
        for (int kk = 0; kk < 32; kk++) {
            float a[4], v[4];
#pragma unroll
            for (int i = 0; i < 4; i++) a[i] = As[kk][trow + i];
#pragma unroll
            for (int j = 0; j < 4; j++) v[j] = Vs[kk][tcol + j];
#pragma unroll
            for (int i = 0; i < 4; i++)
#pragma unroll
                for (int j = 0; j < 4; j++) acc[i][j] += a[i] * v[j];
        }
        __syncthreads();
    }

#pragma unroll
    for (int i = 0; i < 4; i++) {
        float4 v;
        v.x = acc[i][0]; v.y = acc[i][1]; v.z = acc[i][2]; v.w = acc[i][3];
        *(float4*)&ctx[(size_t)(b * SS + sq0 + trow + i) * EE + hq * HD + tcol] = v;
    }
}

// ---------------------------------------------------------------------------
extern "C" void kernel_launch(void* const* d_in, const int* in_sizes, int n_in,
                              void* d_out, int out_size)
{
    const float* query = (const float*)d_in[0];
    const float* key   = (const float*)d_in[1];
    const float* value = (const float*)d_in[2];
    const float* Wq    = (const float*)d_in[3];
    const float* bq    = (const float*)d_in[4];
    const float* Wk    = (const float*)d_in[5];
    const float* bk    = (const float*)d_in[6];
    const float* Wv    = (const float*)d_in[7];
    const float* bv    = (const float*)d_in[8];
    const float* Wo    = (const float*)d_in[9];
    const float* bo    = (const float*)d_in[10];

    float* out  = (float*)d_out;                       // (B, S, E)
    float* attn = out + (size_t)BB * SS * EE;          // (B, HQ, S, S)

    float *qs, *ks, *vs, *cs;
    cudaGetSymbolAddress((void**)&qs, g_Q);
    cudaGetSymbolAddress((void**)&ks, g_K);
    cudaGetSymbolAddress((void**)&vs, g_V);
    cudaGetSymbolAddress((void**)&cs, g_CTX);

    // 1-3. Projections
    sgemm_bias_kernel<<<dim3(EE / 128, MM / 128), 256>>>(query, Wq, bq, qs, MM, EE, EE);
    sgemm_bias_kernel<<<dim3(KV / 128, MM / 128), 256>>>(key,   Wk, bk, ks, MM, KV, EE);
    sgemm_bias_kernel<<<dim3(KV / 128, MM / 128), 256>>>(value, Wv, bv, vs, MM, KV, EE);

    // 4. Scores -> attn region of d_out (pre-softmax)
    scores_kernel<<<dim3(SS / 64, SS / 64, BB * HQ), 256>>>(qs, ks, attn);

    // 5. Softmax in place
    softmax_kernel<<<dim3(BB * HQ * SS), 256>>>(attn);

    // 6. attn @ V -> ctx
    av_kernel<<<dim3(1, SS / 64, BB * HQ), 256>>>(attn, vs, cs);

    // 7. Output projection -> out region of d_out
    sgemm_bias_kernel<<<dim3(EE / 128, MM / 128), 256>>>(cs, Wo, bo, out, MM, EE, EE);
}

// round 2
// speedup vs baseline: 2.3002x; 2.3002x over previous
#include <cuda_runtime.h>
#include <cstdint>

// Problem constants
#define BB   2
#define SS   2048
#define EE   2048
#define HQ   32
#define HKV  8
#define HD   64
#define KV   512
#define MM   (BB*SS)         // 4096
#define SCALE 0.125f         // 1/sqrt(64)

// Scratch (device globals; no allocation allowed)
__device__ float g_Q[MM*EE];
__device__ float g_K[MM*KV];
__device__ float g_V[MM*KV];
__device__ float g_CTX[MM*EE];

// ---------------------------------------------------------------------------
// TF32 helpers
// ---------------------------------------------------------------------------
__device__ __forceinline__ uint32_t f2tf(float f) {
    uint32_t r;
    asm("cvt.rna.tf32.f32 %0, %1;" : "=r"(r) : "f"(f));
    return r;
}

__device__ __forceinline__ void mma8(float* c, const uint32_t* a, const uint32_t* b) {
    asm volatile(
        "mma.sync.aligned.m16n8k8.row.col.f32.tf32.tf32.f32 "
        "{%0,%1,%2,%3}, {%4,%5,%6,%7}, {%8,%9}, {%0,%1,%2,%3};\n"
        : "+f"(c[0]), "+f"(c[1]), "+f"(c[2]), "+f"(c[3])
        : "r"(a[0]), "r"(a[1]), "r"(a[2]), "r"(a[3]), "r"(b[0]), "r"(b[1]));
}

// ---------------------------------------------------------------------------
// Projection GEMM: C[M,N] = A[M,K] @ W[K,N] + bias
// BM=128, BN=128, BK=32; 8 warps (2x4); warp tile 64x32.
// ---------------------------------------------------------------------------
__global__ __launch_bounds__(256) void proj_tf32_kernel(
    const float* __restrict__ A, const float* __restrict__ W,
    const float* __restrict__ bias, float* __restrict__ C,
    int M, int N, int K)
{
    __shared__ uint32_t As[128][36];    // [m][k], bank = (4m+k)%32
    __shared__ uint32_t Ws[32][136];    // [k][n], bank = (8k+n)%32

    const int tid  = threadIdx.x;
    const int row0 = blockIdx.y * 128;
    const int col0 = blockIdx.x * 128;
    const int warp = tid >> 5, lane = tid & 31;
    const int qr = lane >> 2, qc = lane & 3;
    const int wm = (warp >> 2) * 64, wn = (warp & 3) * 32;

    float acc[4][4][4] = {};

    for (int k0 = 0; k0 < K; k0 += 32) {
#pragma unroll
        for (int it = 0; it < 4; it++) {
            int idx = tid + it * 256;
            int r = idx >> 3, c = (idx & 7) * 4;
            float4 v = *(const float4*)&A[(size_t)(row0 + r) * K + k0 + c];
            uint4 u = make_uint4(f2tf(v.x), f2tf(v.y), f2tf(v.z), f2tf(v.w));
            *(uint4*)&As[r][c] = u;
        }
#pragma unroll
        for (int it = 0; it < 4; it++) {
            int idx = tid + it * 256;
            int r = idx >> 5, c = (idx & 31) * 4;
            float4 v = *(const float4*)&W[(size_t)(k0 + r) * N + col0 + c];
            uint4 u = make_uint4(f2tf(v.x), f2tf(v.y), f2tf(v.z), f2tf(v.w));
            *(uint4*)&Ws[r][c] = u;
        }
        __syncthreads();

#pragma unroll
        for (int kk = 0; kk < 32; kk += 8) {
            uint32_t a[4][4], b[4][2];
#pragma unroll
            for (int mi = 0; mi < 4; mi++) {
                int m = wm + mi * 16 + qr;
                a[mi][0] = As[m][kk + qc];
                a[mi][1] = As[m + 8][kk + qc];
                a[mi][2] = As[m][kk + qc + 4];
                a[mi][3] = As[m + 8][kk + qc + 4];
            }
#pragma unroll
            for (int ni = 0; ni < 4; ni++) {
                int n = wn + ni * 8 + qr;
                b[ni][0] = Ws[kk + qc][n];
                b[ni][1] = Ws[kk + qc + 4][n];
            }
#pragma unroll
            for (int mi = 0; mi < 4; mi++)
#pragma unroll
                for (int ni = 0; ni < 4; ni++)
                    mma8(acc[mi][ni], a[mi], b[ni]);
        }
        __syncthreads();
    }

#pragma unroll
    for (int mi = 0; mi < 4; mi++) {
        int row = row0 + wm + mi * 16 + qr;
#pragma unroll
        for (int ni = 0; ni < 4; ni++) {
            int col = col0 + wn + ni * 8 + 2 * qc;
            float2 bb = *(const float2*)&bias[col];
            float2 v0 = make_float2(acc[mi][ni][0] + bb.x, acc[mi][ni][1] + bb.y);
            float2 v1 = make_float2(acc[mi][ni][2] + bb.x, acc[mi][ni][3] + bb.y);
            *(float2*)&C[(size_t)row * N + col]       = v0;
            *(float2*)&C[(size_t)(row + 8) * N + col] = v1;
        }
    }
}

// ---------------------------------------------------------------------------
// Scores: attn[b,hq,sq,sk] = scale * Q'[sq,:] . K'[sk,:]   (K=64)
// BM=128, BN=128, BK=32 (2 iters); both operands k-contiguous.
// ---------------------------------------------------------------------------
__global__ __launch_bounds__(256) void scores_tf32_kernel(
    const float* __restrict__ Q, const float* __restrict__ Kp,
    float* __restrict__ attn)
{
    __shared__ uint32_t As[128][36];    // [sq][d]
    __shared__ uint32_t Bs[128][36];    // [sk][d]

    const int bh = blockIdx.z, b = bh >> 5, hq = bh & 31, hkv = hq >> 2;
    const int sq0 = blockIdx.y * 128, sk0 = blockIdx.x * 128;
    const int tid = threadIdx.x;
    const int warp = tid >> 5, lane = tid & 31;
    const int qr = lane >> 2, qc = lane & 3;
    const int wm = (warp >> 2) * 64, wn = (warp & 3) * 32;

    const float* Abase = Q  + (size_t)(b * SS + sq0) * EE + hq * HD;
    const float* Bbase = Kp + (size_t)(b * SS + sk0) * KV + hkv * HD;

    float acc[4][4][4] = {};

#pragma unroll
    for (int k0 = 0; k0 < 64; k0 += 32) {
#pragma unroll
        for (int it = 0; it < 4; it++) {
            int idx = tid + it * 256;
            int r = idx >> 3, c = (idx & 7) * 4;
            float4 v = *(const float4*)&Abase[(size_t)r * EE + k0 + c];
            *(uint4*)&As[r][c] = make_uint4(f2tf(v.x), f2tf(v.y), f2tf(v.z), f2tf(v.w));
        }
#pragma unroll
        for (int it = 0; it < 4; it++) {
            int idx = tid + it * 256;
            int r = idx >> 3, c = (idx & 7) * 4;
            float4 v = *(const float4*)&Bbase[(size_t)r * KV + k0 + c];
            *(uint4*)&Bs[r][c] = make_uint4(f2tf(v.x), f2tf(v.y), f2tf(v.z), f2tf(v.w));
        }
        __syncthreads();

#pragma unroll
        for (int kk = 0; kk < 32; kk += 8) {
            uint32_t a[4][4], bf[4][2];
#pragma unroll
            for (int mi = 0; mi < 4; mi++) {
                int m = wm + mi * 16 + qr;
                a[mi][0] = As[m][kk + qc];
                a[mi][1] = As[m + 8][kk + qc];
                a[mi][2] = As[m][kk + qc + 4];
                a[mi][3] = As[m + 8][kk + qc + 4];
            }
#pragma unroll
            for (int ni = 0; ni < 4; ni++) {
                int n = wn + ni * 8 + qr;
                bf[ni][0] = Bs[n][kk + qc];
                bf[ni][1] = Bs[n][kk + qc + 4];
            }
#pragma unroll
            for (int mi = 0; mi < 4; mi++)
#pragma unroll
                for (int ni = 0; ni < 4; ni++)
                    mma8(acc[mi][ni], a[mi], bf[ni]);
        }
        __syncthreads();
    }

    float* Cbase = attn + ((size_t)bh * SS + sq0) * SS + sk0;
#pragma unroll
    for (int mi = 0; mi < 4; mi++) {
        int row = wm + mi * 16 + qr;
#pragma unroll
        for (int ni = 0; ni < 4; ni++) {
            int col = wn + ni * 8 + 2 * qc;
            float2 v0 = make_float2(acc[mi][ni][0] * SCALE, acc[mi][ni][1] * SCALE);
            float2 v1 = make_float2(acc[mi][ni][2] * SCALE, acc[mi][ni][3] * SCALE);
            *(float2*)&Cbase[(size_t)row * SS + col]       = v0;
            *(float2*)&Cbase[(size_t)(row + 8) * SS + col] = v1;
        }
    }
}

// ---------------------------------------------------------------------------
// In-place row softmax over last dim (2048). One block (256 thr) per row.
// ---------------------------------------------------------------------------
__global__ __launch_bounds__(256) void softmax_kernel(float* __restrict__ attn)
{
    float* p = attn + (size_t)blockIdx.x * SS;
    const int t = threadIdx.x;

    float4 a = ((float4*)p)[t];
    float4 b = ((float4*)p)[t + 256];

    float m = fmaxf(fmaxf(fmaxf(a.x, a.y), fmaxf(a.z, a.w)),
                    fmaxf(fmaxf(b.x, b.y), fmaxf(b.z, b.w)));
#pragma unroll
    for (int o = 16; o; o >>= 1) m = fmaxf(m, __shfl_xor_sync(0xffffffffu, m, o));

    __shared__ float sm[8], ssum[8];
    if ((t & 31) == 0) sm[t >> 5] = m;
    __syncthreads();
    m = sm[0];
#pragma unroll
    for (int i = 1; i < 8; i++) m = fmaxf(m, sm[i]);

    a.x = __expf(a.x - m); a.y = __expf(a.y - m);
    a.z = __expf(a.z - m); a.w = __expf(a.w - m);
    b.x = __expf(b.x - m); b.y = __expf(b.y - m);
    b.z = __expf(b.z - m); b.w = __expf(b.w - m);

    float s = a.x + a.y + a.z + a.w + b.x + b.y + b.z + b.w;
#pragma unroll
    for (int o = 16; o; o >>= 1) s += __shfl_xor_sync(0xffffffffu, s, o);
    if ((t & 31) == 0) ssum[t >> 5] = s;
    __syncthreads();
    s = 0.f;
#pragma unroll
    for (int i = 0; i < 8; i++) s += ssum[i];

    const float inv = 1.0f / s;
    a.x *= inv; a.y *= inv; a.z *= inv; a.w *= inv;
    b.x *= inv; b.y *= inv; b.z *= inv; b.w *= inv;
    ((float4*)p)[t] = a;
    ((float4*)p)[t + 256] = b;
}

// ---------------------------------------------------------------------------
// AV: ctx[b,sq,hq*64+d] = sum_sk attn[b,hq,sq,sk] * V[b,sk,hq/4,d]
// BM=128, BN=64, BK=32; 8 warps (4x2); warp tile 32x32.
// ---------------------------------------------------------------------------
__global__ __launch_bounds__(256) void av_tf32_kernel(
    const float* __restrict__ attn, const float* __restrict__ Vp,
    float* __restrict__ ctx)
{
    __shared__ uint32_t As[128][36];    // [sq][sk]
    __shared__ uint32_t Bs[64][33];     // [d][sk] (V transposed), bank = (n+k)%32

    const int bh = blockIdx.z, b = bh >> 5, hq = bh & 31, hkv = hq >> 2;
    const int sq0 = blockIdx.y * 128;
    const int tid = threadIdx.x;
    const int warp = tid >> 5, lane = tid & 31;
    const int qr = lane >> 2, qc = lane & 3;
    const int wm = (warp >> 1) * 32, wn = (warp & 1) * 32;

    const float* Abase = attn + ((size_t)bh * SS + sq0) * SS;
    const float* Bbase = Vp + (size_t)(b * SS) * KV + hkv * HD;

    float acc[2][4][4] = {};

    for (int k0 = 0; k0 < SS; k0 += 32) {
#pragma unroll
        for (int it = 0; it < 4; it++) {
            int idx = tid + it * 256;
            int r = idx >> 3, c = (idx & 7) * 4;
            float4 v = *(const float4*)&Abase[(size_t)r * SS + k0 + c];
            *(uint4*)&As[r][c] = make_uint4(f2tf(v.x), f2tf(v.y), f2tf(v.z), f2tf(v.w));
        }
        // V tile: 32(k) x 64(n), scalar coalesced loads, transposed store
#pragma unroll
        for (int it = 0; it < 8; it++) {
            int idx = tid + it * 256;
            int n = idx & 63, k = idx >> 6;
            Bs[n][k] = f2tf(Bbase[(size_t)(k0 + k) * KV + n]);
        }
        __syncthreads();

#pragma unroll
        for (int kk = 0; kk < 32; kk += 8) {
            uint32_t a[2][4], bf[4][2];
#pragma unroll
            for (int mi = 0; mi < 2; mi++) {
                int m = wm + mi * 16 + qr;
                a[mi][0] = As[m][kk + qc];
                a[mi][1] = As[m + 8][kk + qc];
                a[mi][2] = As[m][kk + qc + 4];
                a[mi][3] = As[m + 8][kk + qc + 4];
            }
#pragma unroll
            for (int ni = 0; ni < 4; ni++) {
                int n = wn + ni * 8 + qr;
                bf[ni][0] = Bs[n][kk + qc];
                bf[ni][1] = Bs[n][kk + qc + 4];
            }
#pragma unroll
            for (int mi = 0; mi < 2; mi++)
#pragma unroll
                for (int ni = 0; ni < 4; ni++)
                    mma8(acc[mi][ni], a[mi], bf[ni]);
        }
        __syncthreads();
    }

#pragma unroll
    for (int mi = 0; mi < 2; mi++) {
        int row = sq0 + wm + mi * 16 + qr;
#pragma unroll
        for (int ni = 0; ni < 4; ni++) {
            int col = wn + ni * 8 + 2 * qc;
            float2 v0 = make_float2(acc[mi][ni][0], acc[mi][ni][1]);
            float2 v1 = make_float2(acc[mi][ni][2], acc[mi][ni][3]);
            *(float2*)&ctx[(size_t)(b * SS + row) * EE + hq * HD + col]     = v0;
            *(float2*)&ctx[(size_t)(b * SS + row + 8) * EE + hq * HD + col] = v1;
        }
    }
}

// ---------------------------------------------------------------------------
extern "C" void kernel_launch(void* const* d_in, const int* in_sizes, int n_in,
                              void* d_out, int out_size)
{
    const float* query = (const float*)d_in[0];
    const float* key   = (const float*)d_in[1];
    const float* value = (const float*)d_in[2];
    const float* Wq    = (const float*)d_in[3];
    const float* bq    = (const float*)d_in[4];
    const float* Wk    = (const float*)d_in[5];
    const float* bk    = (const float*)d_in[6];
    const float* Wv    = (const float*)d_in[7];
    const float* bv    = (const float*)d_in[8];
    const float* Wo    = (const float*)d_in[9];
    const float* bo    = (const float*)d_in[10];

    float* out  = (float*)d_out;                       // (B, S, E)
    float* attn = out + (size_t)BB * SS * EE;          // (B, HQ, S, S)

    float *qs, *ks, *vs, *cs;
    cudaGetSymbolAddress((void**)&qs, g_Q);
    cudaGetSymbolAddress((void**)&ks, g_K);
    cudaGetSymbolAddress((void**)&vs, g_V);
    cudaGetSymbolAddress((void**)&cs, g_CTX);

    // 1-3. Projections (TF32 tensor cores)
    proj_tf32_kernel<<<dim3(EE / 128, MM / 128), 256>>>(query, Wq, bq, qs, MM, EE, EE);
    proj_tf32_kernel<<<dim3(KV / 128, MM / 128), 256>>>(key,   Wk, bk, ks, MM, KV, EE);
    proj_tf32_kernel<<<dim3(KV / 128, MM / 128), 256>>>(value, Wv, bv, vs, MM, KV, EE);

    // 4. Scores -> attn region of d_out (pre-softmax)
    scores_tf32_kernel<<<dim3(SS / 128, SS / 128, BB * HQ), 256>>>(qs, ks, attn);

    // 5. Softmax in place
    softmax_kernel<<<dim3(BB * HQ * SS), 256>>>(attn);

    // 6. attn @ V -> ctx
    av_tf32_kernel<<<dim3(1, SS / 128, BB * HQ), 256>>>(attn, vs, cs);

    // 7. Output projection -> out region of d_out
    proj_tf32_kernel<<<dim3(EE / 128, MM / 128), 256>>>(cs, Wo, bo, out, MM, EE, EE);
}